// round 2
// baseline (speedup 1.0000x reference)
#include <cuda_runtime.h>
#include <math.h>

#define BB 8
#define TT 2048
#define DD 1024
#define HS 64

// Staging buffers for Q,K,V projections (no cudaMalloc allowed)
__device__ float g_Q[BB * TT * HS];
__device__ float g_K[BB * TT * HS];
__device__ float g_V[BB * TT * HS];

// ---------------------------------------------------------------------------
// Kernel 1: fused QKV projection.
// Grid: 16384/64 = 256 blocks, 256 threads. Each block: 64 rows x 64 cols x 3.
// Register tile 4x4 per thread per matrix (48 accumulators).
// ---------------------------------------------------------------------------
__global__ void qkv_proj(const float* __restrict__ x,
                         const float* __restrict__ Wq, const float* __restrict__ bq,
                         const float* __restrict__ Wk, const float* __restrict__ bk,
                         const float* __restrict__ Wv, const float* __restrict__ bv) {
    __shared__ float xs[64][36];        // pad 36 (144B, float4-aligned, kills bank repeat)
    __shared__ float ws0[32][64];
    __shared__ float ws1[32][64];
    __shared__ float ws2[32][64];

    const int tid = threadIdx.x;
    const int tx = tid & 15;            // col group
    const int ty = tid >> 4;            // row group
    const int row0 = blockIdx.x * 64;

    float acc[3][4][4];
#pragma unroll
    for (int m = 0; m < 3; m++)
#pragma unroll
        for (int r = 0; r < 4; r++)
#pragma unroll
            for (int c = 0; c < 4; c++) acc[m][r][c] = 0.f;

    for (int k0 = 0; k0 < DD; k0 += 32) {
        __syncthreads();
        // x tile: 64 rows x 32 k = 512 float4, 2 per thread
#pragma unroll
        for (int l = 0; l < 2; l++) {
            int f  = tid + l * 256;      // 0..511
            int r  = f >> 3;             // 8 float4 per row
            int c4 = f & 7;
            float4 v = *reinterpret_cast<const float4*>(
                &x[(size_t)(row0 + r) * DD + k0 + c4 * 4]);
            *reinterpret_cast<float4*>(&xs[r][c4 * 4]) = v;
        }
        // W tiles: 32 x 64 each = 512 float4, 2 per thread per matrix
#pragma unroll
        for (int l = 0; l < 2; l++) {
            int f  = tid + l * 256;
            int r  = f >> 4;             // 16 float4 per row
            int c4 = f & 15;
            *reinterpret_cast<float4*>(&ws0[r][c4 * 4]) =
                *reinterpret_cast<const float4*>(&Wq[(size_t)(k0 + r) * HS + c4 * 4]);
            *reinterpret_cast<float4*>(&ws1[r][c4 * 4]) =
                *reinterpret_cast<const float4*>(&Wk[(size_t)(k0 + r) * HS + c4 * 4]);
            *reinterpret_cast<float4*>(&ws2[r][c4 * 4]) =
                *reinterpret_cast<const float4*>(&Wv[(size_t)(k0 + r) * HS + c4 * 4]);
        }
        __syncthreads();

#pragma unroll
        for (int kk = 0; kk < 32; kk++) {
            float xv[4];
#pragma unroll
            for (int r = 0; r < 4; r++) xv[r] = xs[ty * 4 + r][kk];
            float4 w0 = *reinterpret_cast<const float4*>(&ws0[kk][tx * 4]);
            float4 w1 = *reinterpret_cast<const float4*>(&ws1[kk][tx * 4]);
            float4 w2 = *reinterpret_cast<const float4*>(&ws2[kk][tx * 4]);
#pragma unroll
            for (int r = 0; r < 4; r++) {
                acc[0][r][0] += xv[r] * w0.x; acc[0][r][1] += xv[r] * w0.y;
                acc[0][r][2] += xv[r] * w0.z; acc[0][r][3] += xv[r] * w0.w;
                acc[1][r][0] += xv[r] * w1.x; acc[1][r][1] += xv[r] * w1.y;
                acc[1][r][2] += xv[r] * w1.z; acc[1][r][3] += xv[r] * w1.w;
                acc[2][r][0] += xv[r] * w2.x; acc[2][r][1] += xv[r] * w2.y;
                acc[2][r][2] += xv[r] * w2.z; acc[2][r][3] += xv[r] * w2.w;
            }
        }
    }

    float4 b0 = *reinterpret_cast<const float4*>(&bq[tx * 4]);
    float4 b1 = *reinterpret_cast<const float4*>(&bk[tx * 4]);
    float4 b2 = *reinterpret_cast<const float4*>(&bv[tx * 4]);
#pragma unroll
    for (int r = 0; r < 4; r++) {
        size_t o = (size_t)(row0 + ty * 4 + r) * HS + tx * 4;
        float4 q = make_float4(acc[0][r][0] + b0.x, acc[0][r][1] + b0.y,
                               acc[0][r][2] + b0.z, acc[0][r][3] + b0.w);
        float4 k = make_float4(acc[1][r][0] + b1.x, acc[1][r][1] + b1.y,
                               acc[1][r][2] + b1.z, acc[1][r][3] + b1.w);
        float4 v = make_float4(acc[2][r][0] + b2.x, acc[2][r][1] + b2.y,
                               acc[2][r][2] + b2.z, acc[2][r][3] + b2.w);
        *reinterpret_cast<float4*>(&g_Q[o]) = q;
        *reinterpret_cast<float4*>(&g_K[o]) = k;
        *reinterpret_cast<float4*>(&g_V[o]) = v;
    }
}

// ---------------------------------------------------------------------------
// Kernel 2: causal flash attention, 64-row q-tiles, 64-wide kv-tiles.
// Grid: (32, 8), 256 threads. Online softmax, 4x4 output tile per thread.
// Dynamic smem layout (floats): Qs[64][68] | Ks[64][65] | Vs[64][64] | Ps[64][65]
// ---------------------------------------------------------------------------
#define QS_PAD 68
#define KS_PAD 65
#define PS_PAD 65
#define SMEM_FLOATS (64 * QS_PAD + 64 * KS_PAD + 64 * 64 + 64 * PS_PAD)
#define SMEM_BYTES (SMEM_FLOATS * 4)

__global__ void flash_attn(float* __restrict__ out) {
    extern __shared__ float sm[];
    float (*Qs)[QS_PAD] = (float(*)[QS_PAD])(sm);
    float (*Ks)[KS_PAD] = (float(*)[KS_PAD])(sm + 64 * QS_PAD);
    float (*Vs)[64]     = (float(*)[64])(sm + 64 * QS_PAD + 64 * KS_PAD);
    float (*Ps)[PS_PAD] = (float(*)[PS_PAD])(sm + 64 * QS_PAD + 64 * KS_PAD + 64 * 64);

    const int tid = threadIdx.x;
    const int tx = tid & 15;
    const int ty = tid >> 4;
    const int b  = blockIdx.y;
    const int q0 = blockIdx.x * 64;

    const float* Qg = g_Q + ((size_t)b * TT + q0) * HS;

    // Load Q tile: 64x64 = 1024 float4, 4 per thread
#pragma unroll
    for (int l = 0; l < 4; l++) {
        int f  = tid + l * 256;
        int r  = f >> 4;
        int c4 = f & 15;
        float4 v = *reinterpret_cast<const float4*>(&Qg[(size_t)r * HS + c4 * 4]);
        *reinterpret_cast<float4*>(&Qs[r][c4 * 4]) = v;
    }

    float mrow[4], lrow[4], o[4][4];
#pragma unroll
    for (int r = 0; r < 4; r++) {
        mrow[r] = -INFINITY;
        lrow[r] = 0.f;
#pragma unroll
        for (int c = 0; c < 4; c++) o[r][c] = 0.f;
    }

    const float scale = 0.125f;  // 1/sqrt(64)

    for (int j0 = 0; j0 <= q0; j0 += 64) {
        __syncthreads();  // previous PV done; safe to overwrite Ks/Vs
        const float* Kg = g_K + ((size_t)b * TT + j0) * HS;
        const float* Vg = g_V + ((size_t)b * TT + j0) * HS;
#pragma unroll
        for (int l = 0; l < 4; l++) {
            int f  = tid + l * 256;
            int r  = f >> 4;
            int c4 = f & 15;
            float4 kv = *reinterpret_cast<const float4*>(&Kg[(size_t)r * HS + c4 * 4]);
            Ks[r][c4 * 4 + 0] = kv.x; Ks[r][c4 * 4 + 1] = kv.y;
            Ks[r][c4 * 4 + 2] = kv.z; Ks[r][c4 * 4 + 3] = kv.w;
            float4 vv = *reinterpret_cast<const float4*>(&Vg[(size_t)r * HS + c4 * 4]);
            *reinterpret_cast<float4*>(&Vs[r][c4 * 4]) = vv;
        }
        __syncthreads();

        // S = Q K^T for this thread's 4x4 tile
        float s[4][4];
#pragma unroll
        for (int r = 0; r < 4; r++)
#pragma unroll
            for (int c = 0; c < 4; c++) s[r][c] = 0.f;

#pragma unroll 8
        for (int h = 0; h < 64; h++) {
            float qv[4], kv[4];
#pragma unroll
            for (int r = 0; r < 4; r++) qv[r] = Qs[ty * 4 + r][h];
#pragma unroll
            for (int c = 0; c < 4; c++) kv[c] = Ks[tx * 4 + c][h];
#pragma unroll
            for (int r = 0; r < 4; r++)
#pragma unroll
                for (int c = 0; c < 4; c++) s[r][c] += qv[r] * kv[c];
        }

        // scale + causal mask (mask -> -inf; exp(-inf - m) = 0)
        const bool diag = (j0 == q0);
#pragma unroll
        for (int r = 0; r < 4; r++) {
            int qg = q0 + ty * 4 + r;
#pragma unroll
            for (int c = 0; c < 4; c++) {
                int kg = j0 + tx * 4 + c;
                s[r][c] *= scale;
                if (diag && kg > qg) s[r][c] = -INFINITY;
            }
        }

        // online softmax update
        float p[4][4];
#pragma unroll
        for (int r = 0; r < 4; r++) {
            float rm = fmaxf(fmaxf(s[r][0], s[r][1]), fmaxf(s[r][2], s[r][3]));
#pragma unroll
            for (int off = 8; off >= 1; off >>= 1)
                rm = fmaxf(rm, __shfl_xor_sync(0xffffffffu, rm, off));
            float mnew = fmaxf(mrow[r], rm);
            float alpha = __expf(mrow[r] - mnew);
            float rs = 0.f;
#pragma unroll
            for (int c = 0; c < 4; c++) {
                p[r][c] = __expf(s[r][c] - mnew);
                rs += p[r][c];
            }
#pragma unroll
            for (int off = 8; off >= 1; off >>= 1)
                rs += __shfl_xor_sync(0xffffffffu, rs, off);
            lrow[r] = lrow[r] * alpha + rs;
            mrow[r] = mnew;
#pragma unroll
            for (int c = 0; c < 4; c++) o[r][c] *= alpha;
        }

        // publish P
#pragma unroll
        for (int r = 0; r < 4; r++)
#pragma unroll
            for (int c = 0; c < 4; c++)
                Ps[ty * 4 + r][tx * 4 + c] = p[r][c];
        __syncthreads();

        // O += P V
#pragma unroll 8
        for (int k = 0; k < 64; k++) {
            float pv[4];
#pragma unroll
            for (int r = 0; r < 4; r++) pv[r] = Ps[ty * 4 + r][k];
            float4 vv = *reinterpret_cast<const float4*>(&Vs[k][tx * 4]);
#pragma unroll
            for (int r = 0; r < 4; r++) {
                o[r][0] += pv[r] * vv.x; o[r][1] += pv[r] * vv.y;
                o[r][2] += pv[r] * vv.z; o[r][3] += pv[r] * vv.w;
            }
        }
    }

    // normalize + store
#pragma unroll
    for (int r = 0; r < 4; r++) {
        float inv = 1.f / lrow[r];
        size_t off = ((size_t)b * TT + q0 + ty * 4 + r) * HS + tx * 4;
        float4 ov = make_float4(o[r][0] * inv, o[r][1] * inv,
                                o[r][2] * inv, o[r][3] * inv);
        *reinterpret_cast<float4*>(&out[off]) = ov;
    }
}

// ---------------------------------------------------------------------------
extern "C" void kernel_launch(void* const* d_in, const int* in_sizes, int n_in,
                              void* d_out, int out_size) {
    const float* x  = (const float*)d_in[0];
    const float* Wq = (const float*)d_in[1];
    const float* bq = (const float*)d_in[2];
    const float* Wk = (const float*)d_in[3];
    const float* bk = (const float*)d_in[4];
    const float* Wv = (const float*)d_in[5];
    const float* bv = (const float*)d_in[6];
    float* out = (float*)d_out;

    cudaFuncSetAttribute(flash_attn, cudaFuncAttributeMaxDynamicSharedMemorySize,
                         SMEM_BYTES);

    qkv_proj<<<(BB * TT) / 64, 256>>>(x, Wq, bq, Wk, bk, Wv, bv);
    flash_attn<<<dim3(TT / 64, BB), 256, SMEM_BYTES>>>(out);
}

// round 3
// speedup vs baseline: 2.4394x; 2.4394x over previous
#include <cuda_runtime.h>
#include <math.h>
#include <stdint.h>

#define BB 8
#define TT 2048
#define DD 1024
#define HS 64

// Staging buffers for Q,K,V projections (no cudaMalloc allowed)
__device__ float g_Q[BB * TT * HS];
__device__ float g_K[BB * TT * HS];
__device__ float g_V[BB * TT * HS];

// ---------------------------------------------------------------------------
// TF32 helpers
// ---------------------------------------------------------------------------
__device__ __forceinline__ uint32_t f2tf(float f) {
    uint32_t u;
    asm("cvt.rna.tf32.f32 %0, %1;" : "=r"(u) : "f"(f));
    return u;
}

// D += A * B, m16n8k8, A row-major (4 regs), B col-major (2 regs), fp32 accum
__device__ __forceinline__ void mma_tf32(float* d,
                                         uint32_t a0, uint32_t a1, uint32_t a2, uint32_t a3,
                                         uint32_t b0, uint32_t b1) {
    asm volatile(
        "mma.sync.aligned.m16n8k8.row.col.f32.tf32.tf32.f32 "
        "{%0,%1,%2,%3}, {%4,%5,%6,%7}, {%8,%9}, {%0,%1,%2,%3};\n"
        : "+f"(d[0]), "+f"(d[1]), "+f"(d[2]), "+f"(d[3])
        : "r"(a0), "r"(a1), "r"(a2), "r"(a3), "r"(b0), "r"(b1));
}

// ---------------------------------------------------------------------------
// Kernel 1: fused QKV projection with TF32 MMA.
// Grid: 256 blocks x 256 threads. Block tile: 64 rows x 64 cols x 3 matrices.
// Warp grid 4(m) x 2(n): each warp m16 x n32 per matrix (4 m16n8 frags).
// smem pitches: xs 36 (bank = 4g+t4, conflict-free A loads),
//               ws 72 (bank = 8*t4+g, conflict-free B loads).
// ---------------------------------------------------------------------------
#define XS_P 36
#define WS_P 72

__global__ __launch_bounds__(256) void qkv_proj(
    const float* __restrict__ x,
    const float* __restrict__ Wq, const float* __restrict__ bq,
    const float* __restrict__ Wk, const float* __restrict__ bk,
    const float* __restrict__ Wv, const float* __restrict__ bv) {
    __shared__ uint32_t xs[64][XS_P];
    __shared__ uint32_t ws[3][32][WS_P];

    const int tid  = threadIdx.x;
    const int lane = tid & 31;
    const int wid  = tid >> 5;
    const int wm   = wid >> 1;      // 0..3  (m band, 16 rows)
    const int wn   = wid & 1;       // 0..1  (n band, 32 cols)
    const int g    = lane >> 2;     // groupID 0..7
    const int t4   = lane & 3;      // 0..3
    const int row0 = blockIdx.x * 64;

    float acc[3][4][4];
#pragma unroll
    for (int m = 0; m < 3; m++)
#pragma unroll
        for (int nf = 0; nf < 4; nf++)
#pragma unroll
            for (int i = 0; i < 4; i++) acc[m][nf][i] = 0.f;

    for (int k0 = 0; k0 < DD; k0 += 32) {
        __syncthreads();
#pragma unroll
        for (int l = 0; l < 2; l++) {
            int f = tid + l * 256;
            // x tile: 64 x 32 = 512 float4
            {
                int r = f >> 3, c4 = f & 7;
                float4 v = *reinterpret_cast<const float4*>(
                    &x[(size_t)(row0 + r) * DD + k0 + c4 * 4]);
                *reinterpret_cast<uint4*>(&xs[r][c4 * 4]) =
                    make_uint4(f2tf(v.x), f2tf(v.y), f2tf(v.z), f2tf(v.w));
            }
            // W tiles: 32 x 64 = 512 float4 each
            {
                int r = f >> 4, c4 = f & 15;
                size_t go = (size_t)(k0 + r) * HS + c4 * 4;
                float4 q = *reinterpret_cast<const float4*>(&Wq[go]);
                *reinterpret_cast<uint4*>(&ws[0][r][c4 * 4]) =
                    make_uint4(f2tf(q.x), f2tf(q.y), f2tf(q.z), f2tf(q.w));
                float4 k = *reinterpret_cast<const float4*>(&Wk[go]);
                *reinterpret_cast<uint4*>(&ws[1][r][c4 * 4]) =
                    make_uint4(f2tf(k.x), f2tf(k.y), f2tf(k.z), f2tf(k.w));
                float4 v = *reinterpret_cast<const float4*>(&Wv[go]);
                *reinterpret_cast<uint4*>(&ws[2][r][c4 * 4]) =
                    make_uint4(f2tf(v.x), f2tf(v.y), f2tf(v.z), f2tf(v.w));
            }
        }
        __syncthreads();

#pragma unroll
        for (int kf = 0; kf < 4; kf++) {
            int kb = kf * 8;
            uint32_t a0 = xs[wm * 16 + g][kb + t4];
            uint32_t a1 = xs[wm * 16 + g + 8][kb + t4];
            uint32_t a2 = xs[wm * 16 + g][kb + t4 + 4];
            uint32_t a3 = xs[wm * 16 + g + 8][kb + t4 + 4];
#pragma unroll
            for (int m = 0; m < 3; m++) {
#pragma unroll
                for (int nf = 0; nf < 4; nf++) {
                    int n0 = wn * 32 + nf * 8;
                    uint32_t b0 = ws[m][kb + t4][n0 + g];
                    uint32_t b1 = ws[m][kb + t4 + 4][n0 + g];
                    mma_tf32(acc[m][nf], a0, a1, a2, a3, b0, b1);
                }
            }
        }
    }

    // epilogue: add bias, store Q/K/V
    const int r0g = row0 + wm * 16 + g;
#pragma unroll
    for (int nf = 0; nf < 4; nf++) {
        int c0 = wn * 32 + nf * 8 + 2 * t4;
        float bQ0 = bq[c0], bQ1 = bq[c0 + 1];
        float bK0 = bk[c0], bK1 = bk[c0 + 1];
        float bV0 = bv[c0], bV1 = bv[c0 + 1];
        size_t o0 = (size_t)r0g * HS + c0;
        size_t o1 = (size_t)(r0g + 8) * HS + c0;
        *reinterpret_cast<float2*>(&g_Q[o0]) =
            make_float2(acc[0][nf][0] + bQ0, acc[0][nf][1] + bQ1);
        *reinterpret_cast<float2*>(&g_Q[o1]) =
            make_float2(acc[0][nf][2] + bQ0, acc[0][nf][3] + bQ1);
        *reinterpret_cast<float2*>(&g_K[o0]) =
            make_float2(acc[1][nf][0] + bK0, acc[1][nf][1] + bK1);
        *reinterpret_cast<float2*>(&g_K[o1]) =
            make_float2(acc[1][nf][2] + bK0, acc[1][nf][3] + bK1);
        *reinterpret_cast<float2*>(&g_V[o0]) =
            make_float2(acc[2][nf][0] + bV0, acc[2][nf][1] + bV1);
        *reinterpret_cast<float2*>(&g_V[o1]) =
            make_float2(acc[2][nf][2] + bV0, acc[2][nf][3] + bV1);
    }
}

// ---------------------------------------------------------------------------
// Kernel 2: causal flash attention with TF32 MMA.
// Grid (32, 8), 128 threads = 4 warps. Warp w owns q-rows [w*16, w*16+16)
// and the FULL n=64 key/hs width -> all row reductions stay in-warp (quad
// shuffles over t4 only). P routed through per-warp smem (layout fixup
// C-frag -> A-frag), no cross-warp sync needed (syncwarp only).
// Pitches: Qs/Ks/Ps 68 (bank 4g+t4), Vs 72 (bank 8t4+g) -> conflict-free.
// ---------------------------------------------------------------------------
#define QS_P 68
#define KS_P 68
#define VS_P 72
#define PS_P 68
#define SMEM_U32 (64 * QS_P + 64 * KS_P + 64 * VS_P + 64 * PS_P)
#define SMEM_BYTES (SMEM_U32 * 4)

__global__ __launch_bounds__(128) void flash_attn(float* __restrict__ out) {
    extern __shared__ uint32_t sm[];
    uint32_t (*Qs)[QS_P] = reinterpret_cast<uint32_t(*)[QS_P]>(sm);
    uint32_t (*Ks)[KS_P] = reinterpret_cast<uint32_t(*)[KS_P]>(sm + 64 * QS_P);
    uint32_t (*Vs)[VS_P] = reinterpret_cast<uint32_t(*)[VS_P]>(sm + 64 * QS_P + 64 * KS_P);
    uint32_t (*Ps)[PS_P] = reinterpret_cast<uint32_t(*)[PS_P]>(
        sm + 64 * QS_P + 64 * KS_P + 64 * VS_P);

    const int tid  = threadIdx.x;
    const int lane = tid & 31;
    const int wid  = tid >> 5;          // 0..3
    const int m0   = wid * 16;          // warp's q-row band
    const int g    = lane >> 2;
    const int t4   = lane & 3;
    const int b    = blockIdx.y;
    const int q0   = blockIdx.x * 64;

    // Load Q tile (64x64), convert to tf32
    const float* Qg = g_Q + ((size_t)b * TT + q0) * HS;
#pragma unroll
    for (int l = 0; l < 8; l++) {
        int f = tid + l * 128;
        int r = f >> 4, c4 = f & 15;
        float4 v = *reinterpret_cast<const float4*>(&Qg[(size_t)r * HS + c4 * 4]);
        *reinterpret_cast<uint4*>(&Qs[r][c4 * 4]) =
            make_uint4(f2tf(v.x), f2tf(v.y), f2tf(v.z), f2tf(v.w));
    }

    float o[8][4];
#pragma unroll
    for (int nf = 0; nf < 8; nf++)
#pragma unroll
        for (int i = 0; i < 4; i++) o[nf][i] = 0.f;
    float mrow0 = -INFINITY, mrow1 = -INFINITY;
    float lrow0 = 0.f, lrow1 = 0.f;

    const float scale = 0.125f;  // 1/sqrt(64)
    const int qg0 = q0 + m0 + g;
    const int qg1 = qg0 + 8;

    for (int j0 = 0; j0 <= q0; j0 += 64) {
        __syncthreads();  // prior PV reads of Ks/Vs done
        const float* Kg = g_K + ((size_t)b * TT + j0) * HS;
        const float* Vg = g_V + ((size_t)b * TT + j0) * HS;
#pragma unroll
        for (int l = 0; l < 8; l++) {
            int f = tid + l * 128;
            int r = f >> 4, c4 = f & 15;
            float4 kv = *reinterpret_cast<const float4*>(&Kg[(size_t)r * HS + c4 * 4]);
            *reinterpret_cast<uint4*>(&Ks[r][c4 * 4]) =
                make_uint4(f2tf(kv.x), f2tf(kv.y), f2tf(kv.z), f2tf(kv.w));
            float4 vv = *reinterpret_cast<const float4*>(&Vg[(size_t)r * HS + c4 * 4]);
            *reinterpret_cast<uint4*>(&Vs[r][c4 * 4]) =
                make_uint4(f2tf(vv.x), f2tf(vv.y), f2tf(vv.z), f2tf(vv.w));
        }
        __syncthreads();

        // ---- S = Q K^T (m16 x n64 per warp) ----
        float s[8][4];
#pragma unroll
        for (int nf = 0; nf < 8; nf++)
#pragma unroll
            for (int i = 0; i < 4; i++) s[nf][i] = 0.f;

#pragma unroll
        for (int kf = 0; kf < 8; kf++) {
            int kb = kf * 8;
            uint32_t a0 = Qs[m0 + g][kb + t4];
            uint32_t a1 = Qs[m0 + g + 8][kb + t4];
            uint32_t a2 = Qs[m0 + g][kb + t4 + 4];
            uint32_t a3 = Qs[m0 + g + 8][kb + t4 + 4];
#pragma unroll
            for (int nf = 0; nf < 8; nf++) {
                uint32_t b0 = Ks[nf * 8 + g][kb + t4];
                uint32_t b1 = Ks[nf * 8 + g][kb + t4 + 4];
                mma_tf32(s[nf], a0, a1, a2, a3, b0, b1);
            }
        }

        // ---- scale + causal mask + row max ----
        const bool diag = (j0 == q0);
        float rm0 = -INFINITY, rm1 = -INFINITY;
#pragma unroll
        for (int nf = 0; nf < 8; nf++) {
            int c = j0 + nf * 8 + 2 * t4;
            s[nf][0] *= scale; s[nf][1] *= scale;
            s[nf][2] *= scale; s[nf][3] *= scale;
            if (diag) {
                if (c > qg0)     s[nf][0] = -INFINITY;
                if (c + 1 > qg0) s[nf][1] = -INFINITY;
                if (c > qg1)     s[nf][2] = -INFINITY;
                if (c + 1 > qg1) s[nf][3] = -INFINITY;
            }
            rm0 = fmaxf(rm0, fmaxf(s[nf][0], s[nf][1]));
            rm1 = fmaxf(rm1, fmaxf(s[nf][2], s[nf][3]));
        }
        rm0 = fmaxf(rm0, __shfl_xor_sync(0xffffffffu, rm0, 1));
        rm0 = fmaxf(rm0, __shfl_xor_sync(0xffffffffu, rm0, 2));
        rm1 = fmaxf(rm1, __shfl_xor_sync(0xffffffffu, rm1, 1));
        rm1 = fmaxf(rm1, __shfl_xor_sync(0xffffffffu, rm1, 2));

        float mnew0 = fmaxf(mrow0, rm0);
        float mnew1 = fmaxf(mrow1, rm1);
        float alpha0 = __expf(mrow0 - mnew0);
        float alpha1 = __expf(mrow1 - mnew1);

        float rs0 = 0.f, rs1 = 0.f;
#pragma unroll
        for (int nf = 0; nf < 8; nf++) {
            float p0 = __expf(s[nf][0] - mnew0);
            float p1 = __expf(s[nf][1] - mnew0);
            float p2 = __expf(s[nf][2] - mnew1);
            float p3 = __expf(s[nf][3] - mnew1);
            rs0 += p0 + p1;
            rs1 += p2 + p3;
            int c0 = nf * 8 + 2 * t4;
            *reinterpret_cast<uint2*>(&Ps[m0 + g][c0]) =
                make_uint2(f2tf(p0), f2tf(p1));
            *reinterpret_cast<uint2*>(&Ps[m0 + g + 8][c0]) =
                make_uint2(f2tf(p2), f2tf(p3));
        }
        rs0 += __shfl_xor_sync(0xffffffffu, rs0, 1);
        rs0 += __shfl_xor_sync(0xffffffffu, rs0, 2);
        rs1 += __shfl_xor_sync(0xffffffffu, rs1, 1);
        rs1 += __shfl_xor_sync(0xffffffffu, rs1, 2);

        lrow0 = lrow0 * alpha0 + rs0;  mrow0 = mnew0;
        lrow1 = lrow1 * alpha1 + rs1;  mrow1 = mnew1;

#pragma unroll
        for (int nf = 0; nf < 8; nf++) {
            o[nf][0] *= alpha0; o[nf][1] *= alpha0;
            o[nf][2] *= alpha1; o[nf][3] *= alpha1;
        }

        __syncwarp();  // Ps visible within warp (warp-private rows)

        // ---- O += P V (contraction over key index) ----
#pragma unroll
        for (int kf = 0; kf < 8; kf++) {
            int kb = kf * 8;
            uint32_t a0 = Ps[m0 + g][kb + t4];
            uint32_t a1 = Ps[m0 + g + 8][kb + t4];
            uint32_t a2 = Ps[m0 + g][kb + t4 + 4];
            uint32_t a3 = Ps[m0 + g + 8][kb + t4 + 4];
#pragma unroll
            for (int nf = 0; nf < 8; nf++) {
                uint32_t b0 = Vs[kb + t4][nf * 8 + g];
                uint32_t b1 = Vs[kb + t4 + 4][nf * 8 + g];
                mma_tf32(o[nf], a0, a1, a2, a3, b0, b1);
            }
        }
        __syncwarp();  // Ps reads done before next-iteration overwrite
    }

    // normalize + store
    float inv0 = 1.f / lrow0;
    float inv1 = 1.f / lrow1;
    const int row = q0 + m0 + g;
#pragma unroll
    for (int nf = 0; nf < 8; nf++) {
        int c0 = nf * 8 + 2 * t4;
        *reinterpret_cast<float2*>(&out[((size_t)b * TT + row) * HS + c0]) =
            make_float2(o[nf][0] * inv0, o[nf][1] * inv0);
        *reinterpret_cast<float2*>(&out[((size_t)b * TT + row + 8) * HS + c0]) =
            make_float2(o[nf][2] * inv1, o[nf][3] * inv1);
    }
}

// ---------------------------------------------------------------------------
extern "C" void kernel_launch(void* const* d_in, const int* in_sizes, int n_in,
                              void* d_out, int out_size) {
    const float* x  = (const float*)d_in[0];
    const float* Wq = (const float*)d_in[1];
    const float* bq = (const float*)d_in[2];
    const float* Wk = (const float*)d_in[3];
    const float* bk = (const float*)d_in[4];
    const float* Wv = (const float*)d_in[5];
    const float* bv = (const float*)d_in[6];
    float* out = (float*)d_out;

    cudaFuncSetAttribute(flash_attn, cudaFuncAttributeMaxDynamicSharedMemorySize,
                         SMEM_BYTES);

    qkv_proj<<<(BB * TT) / 64, 256>>>(x, Wq, bq, Wk, bk, Wv, bv);
    flash_attn<<<dim3(TT / 64, BB), 128, SMEM_BYTES>>>(out);
}

// round 4
// speedup vs baseline: 2.8921x; 1.1856x over previous
#include <cuda_runtime.h>
#include <math.h>
#include <stdint.h>

#define BB 8
#define TT 2048
#define DD 1024
#define HS 64

// Q/K/V staged as tf32 bit patterns (pre-converted in proj epilogue).
__device__ uint32_t g_Q[BB * TT * HS];
__device__ uint32_t g_K[BB * TT * HS];
__device__ uint32_t g_V[BB * TT * HS];

// ---------------------------------------------------------------------------
__device__ __forceinline__ uint32_t f2tf(float f) {
    uint32_t u;
    asm("cvt.rna.tf32.f32 %0, %1;" : "=r"(u) : "f"(f));
    return u;
}

__device__ __forceinline__ void mma_tf32(float* d,
                                         uint32_t a0, uint32_t a1, uint32_t a2, uint32_t a3,
                                         uint32_t b0, uint32_t b1) {
    asm volatile(
        "mma.sync.aligned.m16n8k8.row.col.f32.tf32.tf32.f32 "
        "{%0,%1,%2,%3}, {%4,%5,%6,%7}, {%8,%9}, {%0,%1,%2,%3};\n"
        : "+f"(d[0]), "+f"(d[1]), "+f"(d[2]), "+f"(d[3])
        : "r"(a0), "r"(a1), "r"(a2), "r"(a3), "r"(b0), "r"(b1));
}

#define CP_ASYNC16(dst_u32_bytes, src_ptr) \
    asm volatile("cp.async.cg.shared.global [%0], [%1], 16;\n" \
                 :: "r"(dst_u32_bytes), "l"(src_ptr))
#define CP_COMMIT() asm volatile("cp.async.commit_group;\n" ::: "memory")
#define CP_WAIT(n)  asm volatile("cp.async.wait_group %0;\n" :: "n"(n) : "memory")

// ---------------------------------------------------------------------------
// Kernel 1: fused QKV projection, TF32 MMA, register-prefetch double buffer.
// 256 blocks x 256 threads, block tile 64(m) x 64(n) x 3 matrices, k-chunk 32.
// ---------------------------------------------------------------------------
#define XS_P 36
#define WS_P 72

__global__ __launch_bounds__(256) void qkv_proj(
    const float* __restrict__ x,
    const float* __restrict__ Wq, const float* __restrict__ bq,
    const float* __restrict__ Wk, const float* __restrict__ bk,
    const float* __restrict__ Wv, const float* __restrict__ bv) {
    __shared__ uint32_t xs[64][XS_P];
    __shared__ uint32_t ws[3][32][WS_P];

    const int tid  = threadIdx.x;
    const int lane = tid & 31;
    const int wid  = tid >> 5;
    const int wm   = wid >> 1;
    const int wn   = wid & 1;
    const int g    = lane >> 2;
    const int t4   = lane & 3;
    const int row0 = blockIdx.x * 64;

    float acc[3][4][4];
#pragma unroll
    for (int m = 0; m < 3; m++)
#pragma unroll
        for (int nf = 0; nf < 4; nf++)
#pragma unroll
            for (int i = 0; i < 4; i++) acc[m][nf][i] = 0.f;

    // register staging for the next k-chunk
    float4 rx[2], rq[2], rk[2], rv[2];

    // prologue: load chunk 0
#pragma unroll
    for (int l = 0; l < 2; l++) {
        int f = tid + l * 256;
        { int r = f >> 3, c4 = f & 7;
          rx[l] = *reinterpret_cast<const float4*>(&x[(size_t)(row0 + r) * DD + c4 * 4]); }
        { int r = f >> 4, c4 = f & 15;
          size_t go = (size_t)r * HS + c4 * 4;
          rq[l] = *reinterpret_cast<const float4*>(&Wq[go]);
          rk[l] = *reinterpret_cast<const float4*>(&Wk[go]);
          rv[l] = *reinterpret_cast<const float4*>(&Wv[go]); }
    }

    for (int k0 = 0; k0 < DD; k0 += 32) {
        // store staged regs -> smem (with tf32 cvt)
#pragma unroll
        for (int l = 0; l < 2; l++) {
            int f = tid + l * 256;
            { int r = f >> 3, c4 = f & 7;
              *reinterpret_cast<uint4*>(&xs[r][c4 * 4]) =
                  make_uint4(f2tf(rx[l].x), f2tf(rx[l].y), f2tf(rx[l].z), f2tf(rx[l].w)); }
            { int r = f >> 4, c4 = f & 15;
              *reinterpret_cast<uint4*>(&ws[0][r][c4 * 4]) =
                  make_uint4(f2tf(rq[l].x), f2tf(rq[l].y), f2tf(rq[l].z), f2tf(rq[l].w));
              *reinterpret_cast<uint4*>(&ws[1][r][c4 * 4]) =
                  make_uint4(f2tf(rk[l].x), f2tf(rk[l].y), f2tf(rk[l].z), f2tf(rk[l].w));
              *reinterpret_cast<uint4*>(&ws[2][r][c4 * 4]) =
                  make_uint4(f2tf(rv[l].x), f2tf(rv[l].y), f2tf(rv[l].z), f2tf(rv[l].w)); }
        }
        // prefetch next chunk (overlaps the syncs + compute below)
        if (k0 + 32 < DD) {
            int kn = k0 + 32;
#pragma unroll
            for (int l = 0; l < 2; l++) {
                int f = tid + l * 256;
                { int r = f >> 3, c4 = f & 7;
                  rx[l] = *reinterpret_cast<const float4*>(
                      &x[(size_t)(row0 + r) * DD + kn + c4 * 4]); }
                { int r = f >> 4, c4 = f & 15;
                  size_t go = (size_t)(kn + r) * HS + c4 * 4;
                  rq[l] = *reinterpret_cast<const float4*>(&Wq[go]);
                  rk[l] = *reinterpret_cast<const float4*>(&Wk[go]);
                  rv[l] = *reinterpret_cast<const float4*>(&Wv[go]); }
            }
        }
        __syncthreads();

#pragma unroll
        for (int kf = 0; kf < 4; kf++) {
            int kb = kf * 8;
            uint32_t a0 = xs[wm * 16 + g][kb + t4];
            uint32_t a1 = xs[wm * 16 + g + 8][kb + t4];
            uint32_t a2 = xs[wm * 16 + g][kb + t4 + 4];
            uint32_t a3 = xs[wm * 16 + g + 8][kb + t4 + 4];
#pragma unroll
            for (int m = 0; m < 3; m++) {
#pragma unroll
                for (int nf = 0; nf < 4; nf++) {
                    int n0 = wn * 32 + nf * 8;
                    uint32_t b0 = ws[m][kb + t4][n0 + g];
                    uint32_t b1 = ws[m][kb + t4 + 4][n0 + g];
                    mma_tf32(acc[m][nf], a0, a1, a2, a3, b0, b1);
                }
            }
        }
        __syncthreads();  // compute done before next store overwrites smem
    }

    // epilogue: bias add, fold softmax scale into Q, store tf32 bits
    const int r0g = row0 + wm * 16 + g;
#pragma unroll
    for (int nf = 0; nf < 4; nf++) {
        int c0 = wn * 32 + nf * 8 + 2 * t4;
        float bQ0 = bq[c0], bQ1 = bq[c0 + 1];
        float bK0 = bk[c0], bK1 = bk[c0 + 1];
        float bV0 = bv[c0], bV1 = bv[c0 + 1];
        size_t o0 = (size_t)r0g * HS + c0;
        size_t o1 = (size_t)(r0g + 8) * HS + c0;
        *reinterpret_cast<uint2*>(&g_Q[o0]) =
            make_uint2(f2tf((acc[0][nf][0] + bQ0) * 0.125f),
                       f2tf((acc[0][nf][1] + bQ1) * 0.125f));
        *reinterpret_cast<uint2*>(&g_Q[o1]) =
            make_uint2(f2tf((acc[0][nf][2] + bQ0) * 0.125f),
                       f2tf((acc[0][nf][3] + bQ1) * 0.125f));
        *reinterpret_cast<uint2*>(&g_K[o0]) =
            make_uint2(f2tf(acc[1][nf][0] + bK0), f2tf(acc[1][nf][1] + bK1));
        *reinterpret_cast<uint2*>(&g_K[o1]) =
            make_uint2(f2tf(acc[1][nf][2] + bK0), f2tf(acc[1][nf][3] + bK1));
        *reinterpret_cast<uint2*>(&g_V[o0]) =
            make_uint2(f2tf(acc[2][nf][0] + bV0), f2tf(acc[2][nf][1] + bV1));
        *reinterpret_cast<uint2*>(&g_V[o1]) =
            make_uint2(f2tf(acc[2][nf][2] + bV0), f2tf(acc[2][nf][3] + bV1));
    }
}

// ---------------------------------------------------------------------------
// Kernel 2: causal flash attention. 256 threads = 8 warps, q-tile 64.
// Warp grid: wm in 0..3 owns q-rows [wm*16, wm*16+16), wn in 0..1 owns key/hs
// half [wn*32, wn*32+32). Cross-warp (wn pair) softmax reduction via smem.
// K/V double-buffered with cp.async; Q fragments live in registers.
// smem (u32): Ks[2][64][68] | Vs[2][64][72] | Ps[64][68] | red[4][64] floats
// ---------------------------------------------------------------------------
#define KS_P 68
#define VS_P 72
#define PS_P 68
#define OFF_KS 0
#define OFF_VS (2 * 64 * KS_P)
#define OFF_PS (OFF_VS + 2 * 64 * VS_P)
#define OFF_RED (OFF_PS + 64 * PS_P)
#define SMEM_U32 (OFF_RED + 4 * 64)
#define SMEM_BYTES (SMEM_U32 * 4)

__global__ __launch_bounds__(256, 2) void flash_attn(float* __restrict__ out) {
    extern __shared__ uint32_t sm[];
    const uint32_t sb = (uint32_t)__cvta_generic_to_shared(sm);

    uint32_t (*Ps)[PS_P] = reinterpret_cast<uint32_t(*)[PS_P]>(sm + OFF_PS);
    float* redmax = reinterpret_cast<float*>(sm + OFF_RED);        // [2][64]
    float* redsum = reinterpret_cast<float*>(sm + OFF_RED + 128);  // [2][64]

    const int tid  = threadIdx.x;
    const int lane = tid & 31;
    const int wid  = tid >> 5;
    const int wm   = wid & 3;
    const int wn   = wid >> 2;
    const int m0   = wm * 16;
    const int g    = lane >> 2;
    const int t4   = lane & 3;
    const int b    = blockIdx.y;
    const int qt   = 31 - blockIdx.x;   // heavy tiles launch first
    const int q0   = qt * 64;
    const int nt   = qt + 1;            // kv tiles for this block

    const uint32_t* Qg = g_Q + ((size_t)b * TT + q0) * HS;
    const uint32_t* Kb = g_K + (size_t)b * TT * HS;
    const uint32_t* Vb = g_V + (size_t)b * TT * HS;

    // ---- stage Q into Ps region via cp.async, then issue KV tile 0 ----
#pragma unroll
    for (int l = 0; l < 4; l++) {
        int f = tid + l * 256;
        int r = f >> 4, c4 = f & 15;
        CP_ASYNC16(sb + (OFF_PS + r * PS_P + c4 * 4) * 4, Qg + (size_t)r * HS + c4 * 4);
    }
    CP_COMMIT();
#pragma unroll
    for (int l = 0; l < 4; l++) {
        int f = tid + l * 256;
        int r = f >> 4, c4 = f & 15;
        CP_ASYNC16(sb + (OFF_KS + r * KS_P + c4 * 4) * 4, Kb + (size_t)r * HS + c4 * 4);
        CP_ASYNC16(sb + (OFF_VS + r * VS_P + c4 * 4) * 4, Vb + (size_t)r * HS + c4 * 4);
    }
    CP_COMMIT();
    CP_WAIT(1);             // Q staged (KV0 may still be in flight)
    __syncthreads();

    // Q fragments -> registers (reused every iteration)
    uint32_t aq[8][4];
#pragma unroll
    for (int kf = 0; kf < 8; kf++) {
        int kb = kf * 8;
        aq[kf][0] = Ps[m0 + g][kb + t4];
        aq[kf][1] = Ps[m0 + g + 8][kb + t4];
        aq[kf][2] = Ps[m0 + g][kb + t4 + 4];
        aq[kf][3] = Ps[m0 + g + 8][kb + t4 + 4];
    }
    __syncthreads();        // Ps reads done; reusable as P buffer

    float o[4][4];
#pragma unroll
    for (int nf = 0; nf < 4; nf++)
#pragma unroll
        for (int i = 0; i < 4; i++) o[nf][i] = 0.f;
    float mrow0 = -INFINITY, mrow1 = -INFINITY;
    float lrow0 = 0.f, lrow1 = 0.f;

    const int qg0 = q0 + m0 + g;
    const int qg1 = qg0 + 8;

    for (int it = 0; it < nt; it++) {
        const int cur = it & 1;
        __syncthreads();    // prev iter's reads of stage cur^1 complete

        if (it + 1 < nt) {
            const int nx = cur ^ 1;
            const uint32_t* Kg = Kb + (size_t)(it + 1) * 64 * HS;
            const uint32_t* Vg = Vb + (size_t)(it + 1) * 64 * HS;
#pragma unroll
            for (int l = 0; l < 4; l++) {
                int f = tid + l * 256;
                int r = f >> 4, c4 = f & 15;
                CP_ASYNC16(sb + (OFF_KS + (nx * 64 + r) * KS_P + c4 * 4) * 4,
                           Kg + (size_t)r * HS + c4 * 4);
                CP_ASYNC16(sb + (OFF_VS + (nx * 64 + r) * VS_P + c4 * 4) * 4,
                           Vg + (size_t)r * HS + c4 * 4);
            }
            CP_COMMIT();
            CP_WAIT(1);     // stage cur complete
        } else {
            CP_WAIT(0);
        }
        __syncthreads();

        const uint32_t* Ksc = sm + OFF_KS + cur * 64 * KS_P;
        const uint32_t* Vsc = sm + OFF_VS + cur * 64 * VS_P;

        // ---- S = Q K^T : per warp m16 x n32 (its wn half) ----
        float s[4][4];
#pragma unroll
        for (int nf = 0; nf < 4; nf++)
#pragma unroll
            for (int i = 0; i < 4; i++) s[nf][i] = 0.f;

#pragma unroll
        for (int kf = 0; kf < 8; kf++) {
            int kb = kf * 8;
#pragma unroll
            for (int nf = 0; nf < 4; nf++) {
                int nr = wn * 32 + nf * 8 + g;
                uint32_t b0 = Ksc[nr * KS_P + kb + t4];
                uint32_t b1 = Ksc[nr * KS_P + kb + t4 + 4];
                mma_tf32(s[nf], aq[kf][0], aq[kf][1], aq[kf][2], aq[kf][3], b0, b1);
            }
        }

        // ---- causal mask + partial row max (scale pre-folded into Q) ----
        const bool diag = (it == qt);
        const int j0 = it * 64;
        float rm0 = -INFINITY, rm1 = -INFINITY;
#pragma unroll
        for (int nf = 0; nf < 4; nf++) {
            if (diag) {
                int c = j0 + wn * 32 + nf * 8 + 2 * t4;
                if (c > qg0)     s[nf][0] = -INFINITY;
                if (c + 1 > qg0) s[nf][1] = -INFINITY;
                if (c > qg1)     s[nf][2] = -INFINITY;
                if (c + 1 > qg1) s[nf][3] = -INFINITY;
            }
            rm0 = fmaxf(rm0, fmaxf(s[nf][0], s[nf][1]));
            rm1 = fmaxf(rm1, fmaxf(s[nf][2], s[nf][3]));
        }
        rm0 = fmaxf(rm0, __shfl_xor_sync(0xffffffffu, rm0, 1));
        rm0 = fmaxf(rm0, __shfl_xor_sync(0xffffffffu, rm0, 2));
        rm1 = fmaxf(rm1, __shfl_xor_sync(0xffffffffu, rm1, 1));
        rm1 = fmaxf(rm1, __shfl_xor_sync(0xffffffffu, rm1, 2));
        if (t4 == 0) {
            redmax[wn * 64 + m0 + g]     = rm0;
            redmax[wn * 64 + m0 + g + 8] = rm1;
        }
        __syncthreads();
        rm0 = fmaxf(rm0, redmax[(wn ^ 1) * 64 + m0 + g]);
        rm1 = fmaxf(rm1, redmax[(wn ^ 1) * 64 + m0 + g + 8]);

        float mnew0 = fmaxf(mrow0, rm0);
        float mnew1 = fmaxf(mrow1, rm1);
        float alpha0 = __expf(mrow0 - mnew0);
        float alpha1 = __expf(mrow1 - mnew1);

        float rs0 = 0.f, rs1 = 0.f;
#pragma unroll
        for (int nf = 0; nf < 4; nf++) {
            float p0 = __expf(s[nf][0] - mnew0);
            float p1 = __expf(s[nf][1] - mnew0);
            float p2 = __expf(s[nf][2] - mnew1);
            float p3 = __expf(s[nf][3] - mnew1);
            rs0 += p0 + p1;
            rs1 += p2 + p3;
            int c0 = wn * 32 + nf * 8 + 2 * t4;
            *reinterpret_cast<uint2*>(&Ps[m0 + g][c0])     = make_uint2(f2tf(p0), f2tf(p1));
            *reinterpret_cast<uint2*>(&Ps[m0 + g + 8][c0]) = make_uint2(f2tf(p2), f2tf(p3));
        }
        rs0 += __shfl_xor_sync(0xffffffffu, rs0, 1);
        rs0 += __shfl_xor_sync(0xffffffffu, rs0, 2);
        rs1 += __shfl_xor_sync(0xffffffffu, rs1, 1);
        rs1 += __shfl_xor_sync(0xffffffffu, rs1, 2);
        if (t4 == 0) {
            redsum[wn * 64 + m0 + g]     = rs0;
            redsum[wn * 64 + m0 + g + 8] = rs1;
        }
        __syncthreads();
        rs0 += redsum[(wn ^ 1) * 64 + m0 + g];
        rs1 += redsum[(wn ^ 1) * 64 + m0 + g + 8];

        lrow0 = lrow0 * alpha0 + rs0;  mrow0 = mnew0;
        lrow1 = lrow1 * alpha1 + rs1;  mrow1 = mnew1;
#pragma unroll
        for (int nf = 0; nf < 4; nf++) {
            o[nf][0] *= alpha0; o[nf][1] *= alpha0;
            o[nf][2] *= alpha1; o[nf][3] *= alpha1;
        }

        // ---- O += P V : per warp m16 x n32 (hs half), contract k=64 ----
#pragma unroll
        for (int kf = 0; kf < 8; kf++) {
            int kb = kf * 8;
            uint32_t a0 = Ps[m0 + g][kb + t4];
            uint32_t a1 = Ps[m0 + g + 8][kb + t4];
            uint32_t a2 = Ps[m0 + g][kb + t4 + 4];
            uint32_t a3 = Ps[m0 + g + 8][kb + t4 + 4];
#pragma unroll
            for (int nf = 0; nf < 4; nf++) {
                int nc = wn * 32 + nf * 8 + g;
                uint32_t b0 = Vsc[(kb + t4) * VS_P + nc];
                uint32_t b1 = Vsc[(kb + t4 + 4) * VS_P + nc];
                mma_tf32(o[nf], a0, a1, a2, a3, b0, b1);
            }
        }
    }

    // normalize + store
    float inv0 = 1.f / lrow0;
    float inv1 = 1.f / lrow1;
    const int row = q0 + m0 + g;
#pragma unroll
    for (int nf = 0; nf < 4; nf++) {
        int c0 = wn * 32 + nf * 8 + 2 * t4;
        *reinterpret_cast<float2*>(&out[((size_t)b * TT + row) * HS + c0]) =
            make_float2(o[nf][0] * inv0, o[nf][1] * inv0);
        *reinterpret_cast<float2*>(&out[((size_t)b * TT + row + 8) * HS + c0]) =
            make_float2(o[nf][2] * inv1, o[nf][3] * inv1);
    }
}

// ---------------------------------------------------------------------------
extern "C" void kernel_launch(void* const* d_in, const int* in_sizes, int n_in,
                              void* d_out, int out_size) {
    const float* x  = (const float*)d_in[0];
    const float* Wq = (const float*)d_in[1];
    const float* bq = (const float*)d_in[2];
    const float* Wk = (const float*)d_in[3];
    const float* bk = (const float*)d_in[4];
    const float* Wv = (const float*)d_in[5];
    const float* bv = (const float*)d_in[6];
    float* out = (float*)d_out;

    cudaFuncSetAttribute(flash_attn, cudaFuncAttributeMaxDynamicSharedMemorySize,
                         SMEM_BYTES);

    qkv_proj<<<(BB * TT) / 64, 256>>>(x, Wq, bq, Wk, bk, Wv, bv);
    flash_attn<<<dim3(TT / 64, BB), 256, SMEM_BYTES>>>(out);
}

// round 5
// speedup vs baseline: 3.7509x; 1.2969x over previous
#include <cuda_runtime.h>
#include <math.h>
#include <stdint.h>

#define BB 8
#define TT 2048
#define DD 1024
#define HS 64

// Q,K: [b][t][h] tf32 bits.  V: TRANSPOSED [b][h][t] tf32 bits.
__device__ uint32_t g_Q[BB * TT * HS];
__device__ uint32_t g_K[BB * TT * HS];
__device__ uint32_t g_V[BB * TT * HS];

// ---------------------------------------------------------------------------
__device__ __forceinline__ uint32_t f2tf(float f) {
    uint32_t u;
    asm("cvt.rna.tf32.f32 %0, %1;" : "=r"(u) : "f"(f));
    return u;
}

__device__ __forceinline__ void mma_tf32(float* d,
                                         uint32_t a0, uint32_t a1, uint32_t a2, uint32_t a3,
                                         uint32_t b0, uint32_t b1) {
    asm volatile(
        "mma.sync.aligned.m16n8k8.row.col.f32.tf32.tf32.f32 "
        "{%0,%1,%2,%3}, {%4,%5,%6,%7}, {%8,%9}, {%0,%1,%2,%3};\n"
        : "+f"(d[0]), "+f"(d[1]), "+f"(d[2]), "+f"(d[3])
        : "r"(a0), "r"(a1), "r"(a2), "r"(a3), "r"(b0), "r"(b1));
}

#define LDSM_X4(r0, r1, r2, r3, addr) \
    asm volatile("ldmatrix.sync.aligned.m8n8.x4.shared.b16 {%0,%1,%2,%3}, [%4];" \
                 : "=r"(r0), "=r"(r1), "=r"(r2), "=r"(r3) : "r"(addr))

#define CP_ASYNC16(dst_bytes, src_ptr) \
    asm volatile("cp.async.cg.shared.global [%0], [%1], 16;\n" \
                 :: "r"(dst_bytes), "l"(src_ptr))
#define CP_COMMIT() asm volatile("cp.async.commit_group;\n" ::: "memory")
#define CP_WAIT(n)  asm volatile("cp.async.wait_group %0;\n" :: "n"(n) : "memory")

#define BARH(id) asm volatile("bar.sync %0, 256;" :: "r"(id) : "memory")

// ---------------------------------------------------------------------------
// Kernel 1: fused QKV projection, TF32 MMA (unchanged except V epilogue:
// V is written TRANSPOSED [b][hs][t] as tf32 bits; Q gets 0.125 folded in).
// ---------------------------------------------------------------------------
#define XS_P 36
#define WS_P 72

__global__ __launch_bounds__(256, 2) void qkv_proj(
    const float* __restrict__ x,
    const float* __restrict__ Wq, const float* __restrict__ bq,
    const float* __restrict__ Wk, const float* __restrict__ bk,
    const float* __restrict__ Wv, const float* __restrict__ bv) {
    __shared__ uint32_t xs[64][XS_P];
    __shared__ uint32_t ws[3][32][WS_P];

    const int tid  = threadIdx.x;
    const int lane = tid & 31;
    const int wid  = tid >> 5;
    const int wm   = wid >> 1;
    const int wn   = wid & 1;
    const int g    = lane >> 2;
    const int t4   = lane & 3;
    const int row0 = blockIdx.x * 64;

    float acc[3][4][4];
#pragma unroll
    for (int m = 0; m < 3; m++)
#pragma unroll
        for (int nf = 0; nf < 4; nf++)
#pragma unroll
            for (int i = 0; i < 4; i++) acc[m][nf][i] = 0.f;

    float4 rx[2], rq[2], rk[2], rv[2];
#pragma unroll
    for (int l = 0; l < 2; l++) {
        int f = tid + l * 256;
        { int r = f >> 3, c4 = f & 7;
          rx[l] = *reinterpret_cast<const float4*>(&x[(size_t)(row0 + r) * DD + c4 * 4]); }
        { int r = f >> 4, c4 = f & 15;
          size_t go = (size_t)r * HS + c4 * 4;
          rq[l] = *reinterpret_cast<const float4*>(&Wq[go]);
          rk[l] = *reinterpret_cast<const float4*>(&Wk[go]);
          rv[l] = *reinterpret_cast<const float4*>(&Wv[go]); }
    }

    for (int k0 = 0; k0 < DD; k0 += 32) {
#pragma unroll
        for (int l = 0; l < 2; l++) {
            int f = tid + l * 256;
            { int r = f >> 3, c4 = f & 7;
              *reinterpret_cast<uint4*>(&xs[r][c4 * 4]) =
                  make_uint4(f2tf(rx[l].x), f2tf(rx[l].y), f2tf(rx[l].z), f2tf(rx[l].w)); }
            { int r = f >> 4, c4 = f & 15;
              *reinterpret_cast<uint4*>(&ws[0][r][c4 * 4]) =
                  make_uint4(f2tf(rq[l].x), f2tf(rq[l].y), f2tf(rq[l].z), f2tf(rq[l].w));
              *reinterpret_cast<uint4*>(&ws[1][r][c4 * 4]) =
                  make_uint4(f2tf(rk[l].x), f2tf(rk[l].y), f2tf(rk[l].z), f2tf(rk[l].w));
              *reinterpret_cast<uint4*>(&ws[2][r][c4 * 4]) =
                  make_uint4(f2tf(rv[l].x), f2tf(rv[l].y), f2tf(rv[l].z), f2tf(rv[l].w)); }
        }
        if (k0 + 32 < DD) {
            int kn = k0 + 32;
#pragma unroll
            for (int l = 0; l < 2; l++) {
                int f = tid + l * 256;
                { int r = f >> 3, c4 = f & 7;
                  rx[l] = *reinterpret_cast<const float4*>(
                      &x[(size_t)(row0 + r) * DD + kn + c4 * 4]); }
                { int r = f >> 4, c4 = f & 15;
                  size_t go = (size_t)(kn + r) * HS + c4 * 4;
                  rq[l] = *reinterpret_cast<const float4*>(&Wq[go]);
                  rk[l] = *reinterpret_cast<const float4*>(&Wk[go]);
                  rv[l] = *reinterpret_cast<const float4*>(&Wv[go]); }
            }
        }
        __syncthreads();

#pragma unroll
        for (int kf = 0; kf < 4; kf++) {
            int kb = kf * 8;
            uint32_t a0 = xs[wm * 16 + g][kb + t4];
            uint32_t a1 = xs[wm * 16 + g + 8][kb + t4];
            uint32_t a2 = xs[wm * 16 + g][kb + t4 + 4];
            uint32_t a3 = xs[wm * 16 + g + 8][kb + t4 + 4];
#pragma unroll
            for (int m = 0; m < 3; m++) {
#pragma unroll
                for (int nf = 0; nf < 4; nf++) {
                    int n0 = wn * 32 + nf * 8;
                    uint32_t b0 = ws[m][kb + t4][n0 + g];
                    uint32_t b1 = ws[m][kb + t4 + 4][n0 + g];
                    mma_tf32(acc[m][nf], a0, a1, a2, a3, b0, b1);
                }
            }
        }
        __syncthreads();
    }

    const int r0g = row0 + wm * 16 + g;
    const int bat = r0g >> 11;           // row0 tiles never straddle batches
    const int trow = r0g & (TT - 1);
#pragma unroll
    for (int nf = 0; nf < 4; nf++) {
        int c0 = wn * 32 + nf * 8 + 2 * t4;
        float bQ0 = bq[c0], bQ1 = bq[c0 + 1];
        float bK0 = bk[c0], bK1 = bk[c0 + 1];
        float bV0 = bv[c0], bV1 = bv[c0 + 1];
        size_t o0 = (size_t)r0g * HS + c0;
        size_t o1 = (size_t)(r0g + 8) * HS + c0;
        *reinterpret_cast<uint2*>(&g_Q[o0]) =
            make_uint2(f2tf((acc[0][nf][0] + bQ0) * 0.125f),
                       f2tf((acc[0][nf][1] + bQ1) * 0.125f));
        *reinterpret_cast<uint2*>(&g_Q[o1]) =
            make_uint2(f2tf((acc[0][nf][2] + bQ0) * 0.125f),
                       f2tf((acc[0][nf][3] + bQ1) * 0.125f));
        *reinterpret_cast<uint2*>(&g_K[o0]) =
            make_uint2(f2tf(acc[1][nf][0] + bK0), f2tf(acc[1][nf][1] + bK1));
        *reinterpret_cast<uint2*>(&g_K[o1]) =
            make_uint2(f2tf(acc[1][nf][2] + bK0), f2tf(acc[1][nf][3] + bK1));
        // V transposed: [b][hs][t]
        size_t vt0 = ((size_t)bat * HS + c0) * TT + trow;
        g_V[vt0]          = f2tf(acc[2][nf][0] + bV0);
        g_V[vt0 + TT]     = f2tf(acc[2][nf][1] + bV1);
        g_V[vt0 + 8]      = f2tf(acc[2][nf][2] + bV0);
        g_V[vt0 + TT + 8] = f2tf(acc[2][nf][3] + bV1);
    }
}

// ---------------------------------------------------------------------------
// Kernel 2: causal flash attention, split-K softmax, ldmatrix fragments.
// 512 threads = two independent 256-thread halves (named barriers 1/2).
// Half h processes q-tile (h==0 ? p : 31-p): every block = 33 kv iterations.
// Within a half: 8 warps, wm=warp&3 -> 16 q-rows, wn=warp>>2 -> 32-key split.
// Each warp: independent online softmax over its key half, o spans full hs.
// End: merge the two key-halves per row via smem.
// ---------------------------------------------------------------------------
#define KS_P 68
#define VT_P 68
#define PS_P 68
#define OFF_K  0
#define OFF_VT (2 * 64 * KS_P)
#define OFF_P  (OFF_VT + 2 * 64 * VT_P)
#define HALF_U32 (OFF_P + 64 * PS_P)
#define SMEM_BYTES (2 * HALF_U32 * 4)
#define NEG_BIG (-1e30f)

__global__ __launch_bounds__(512, 1) void flash_attn(float* __restrict__ out) {
    extern __shared__ uint32_t sm[];

    const int tid  = threadIdx.x;
    const int half = tid >> 8;
    const int ht   = tid & 255;
    const int lane = tid & 31;
    const int wid  = ht >> 5;          // 0..7 within half
    const int wm   = wid & 3;
    const int wn   = wid >> 2;
    const int m0   = wm * 16;
    const int n0   = wn * 32;
    const int g    = lane >> 2;
    const int t4   = lane & 3;
    const int b    = blockIdx.y;
    const int barid = 1 + half;

    const int qt = half ? (31 - (int)blockIdx.x) : (int)blockIdx.x;
    const int q0 = qt * 64;
    const int nt = qt + 1;

    uint32_t* hsm = sm + half * HALF_U32;
    const uint32_t hbase =
        (uint32_t)__cvta_generic_to_shared(sm) + half * HALF_U32 * 4;
    const uint32_t kbase  = hbase + OFF_K * 4;
    const uint32_t vtbase = hbase + OFF_VT * 4;
    const uint32_t pbase  = hbase + OFF_P * 4;

    // ldmatrix per-thread address components
    const int arow = lane & 15;
    const int acol = (lane >> 4) << 2;
    const int brow = (lane & 7) + ((lane >> 4) << 3);
    const int bcol = ((lane >> 3) & 1) << 2;

    const uint32_t* Qg = g_Q + ((size_t)b * TT + q0) * HS;
    const uint32_t* Kb = g_K + (size_t)b * TT * HS;
    const uint32_t* Vb = g_V + (size_t)b * HS * TT;   // transposed

    // ---- prologue: stage Q into P region, then KV tile 0 ----
#pragma unroll
    for (int l = 0; l < 4; l++) {
        int f = ht + l * 256;
        int r = f >> 4, c4 = f & 15;
        CP_ASYNC16(pbase + (r * PS_P + c4 * 4) * 4, Qg + (size_t)r * HS + c4 * 4);
    }
    CP_COMMIT();
#pragma unroll
    for (int l = 0; l < 4; l++) {
        int f = ht + l * 256;
        int r = f >> 4, c4 = f & 15;
        CP_ASYNC16(kbase + (r * KS_P + c4 * 4) * 4, Kb + (size_t)r * HS + c4 * 4);
        CP_ASYNC16(vtbase + (r * VT_P + c4 * 4) * 4, Vb + (size_t)r * TT + c4 * 4);
    }
    CP_COMMIT();
    CP_WAIT(1);
    BARH(barid);

    // Q fragments -> registers
    uint32_t aq[8][4];
#pragma unroll
    for (int kf = 0; kf < 8; kf++) {
        uint32_t addr = pbase + (((m0 + arow) * PS_P) + kf * 8 + acol) * 4;
        LDSM_X4(aq[kf][0], aq[kf][1], aq[kf][2], aq[kf][3], addr);
    }

    float o[8][4];
#pragma unroll
    for (int nf = 0; nf < 8; nf++)
#pragma unroll
        for (int i = 0; i < 4; i++) o[nf][i] = 0.f;
    float mrow0 = NEG_BIG, mrow1 = NEG_BIG;
    float lrow0 = 0.f, lrow1 = 0.f;

    const int qg0 = q0 + m0 + g;
    const int qg1 = qg0 + 8;

    for (int it = 0; it < nt; it++) {
        const int cur = it & 1;
        BARH(barid);   // all warps done reading stage cur^1 (and prologue Q frags done)

        if (it + 1 < nt) {
            const int nx = cur ^ 1;
            const uint32_t* Kg = Kb + (size_t)(it + 1) * 64 * HS;
            const uint32_t* Vg = Vb + (size_t)(it + 1) * 64;
#pragma unroll
            for (int l = 0; l < 4; l++) {
                int f = ht + l * 256;
                int r = f >> 4, c4 = f & 15;
                CP_ASYNC16(kbase + ((nx * 64 + r) * KS_P + c4 * 4) * 4,
                           Kg + (size_t)r * HS + c4 * 4);
                CP_ASYNC16(vtbase + ((nx * 64 + r) * VT_P + c4 * 4) * 4,
                           Vg + (size_t)r * TT + c4 * 4);
            }
            CP_COMMIT();
            CP_WAIT(1);
        } else {
            CP_WAIT(0);
        }
        BARH(barid);   // stage cur visible

        const uint32_t kst  = kbase + cur * 64 * KS_P * 4;
        const uint32_t vtst = vtbase + cur * 64 * VT_P * 4;

        // ---- S = Q K^T : m16 x n32 (warp's key half) ----
        float s[4][4];
#pragma unroll
        for (int nf = 0; nf < 4; nf++)
#pragma unroll
            for (int i = 0; i < 4; i++) s[nf][i] = 0.f;

#pragma unroll
        for (int kf = 0; kf < 8; kf++) {
            int kb = kf * 8;
#pragma unroll
            for (int nfp = 0; nfp < 2; nfp++) {
                uint32_t b0, b1, b2, b3;
                uint32_t addr = kst +
                    ((n0 + nfp * 16 + brow) * KS_P + kb + bcol) * 4;
                LDSM_X4(b0, b1, b2, b3, addr);
                mma_tf32(s[nfp * 2],     aq[kf][0], aq[kf][1], aq[kf][2], aq[kf][3], b0, b1);
                mma_tf32(s[nfp * 2 + 1], aq[kf][0], aq[kf][1], aq[kf][2], aq[kf][3], b2, b3);
            }
        }

        // ---- causal mask + in-warp row max (t4 shuffles only) ----
        const bool diag = (it == qt);
        const int j0 = it * 64;
        float rm0 = NEG_BIG, rm1 = NEG_BIG;
#pragma unroll
        for (int nf = 0; nf < 4; nf++) {
            if (diag) {
                int c = j0 + n0 + nf * 8 + 2 * t4;
                if (c > qg0)     s[nf][0] = NEG_BIG;
                if (c + 1 > qg0) s[nf][1] = NEG_BIG;
                if (c > qg1)     s[nf][2] = NEG_BIG;
                if (c + 1 > qg1) s[nf][3] = NEG_BIG;
            }
            rm0 = fmaxf(rm0, fmaxf(s[nf][0], s[nf][1]));
            rm1 = fmaxf(rm1, fmaxf(s[nf][2], s[nf][3]));
        }
        rm0 = fmaxf(rm0, __shfl_xor_sync(0xffffffffu, rm0, 1));
        rm0 = fmaxf(rm0, __shfl_xor_sync(0xffffffffu, rm0, 2));
        rm1 = fmaxf(rm1, __shfl_xor_sync(0xffffffffu, rm1, 1));
        rm1 = fmaxf(rm1, __shfl_xor_sync(0xffffffffu, rm1, 2));

        float mnew0 = fmaxf(mrow0, rm0);
        float mnew1 = fmaxf(mrow1, rm1);
        float alpha0 = __expf(mrow0 - mnew0);
        float alpha1 = __expf(mrow1 - mnew1);

        __syncwarp();   // prior PV ldmatrix reads of P done before overwrite
        float rs0 = 0.f, rs1 = 0.f;
#pragma unroll
        for (int nf = 0; nf < 4; nf++) {
            float p0 = __expf(s[nf][0] - mnew0);
            float p1 = __expf(s[nf][1] - mnew0);
            float p2 = __expf(s[nf][2] - mnew1);
            float p3 = __expf(s[nf][3] - mnew1);
            rs0 += p0 + p1;
            rs1 += p2 + p3;
            int c0 = n0 + nf * 8 + 2 * t4;
            *reinterpret_cast<uint2*>(&hsm[OFF_P + (m0 + g) * PS_P + c0]) =
                make_uint2(f2tf(p0), f2tf(p1));
            *reinterpret_cast<uint2*>(&hsm[OFF_P + (m0 + g + 8) * PS_P + c0]) =
                make_uint2(f2tf(p2), f2tf(p3));
        }
        rs0 += __shfl_xor_sync(0xffffffffu, rs0, 1);
        rs0 += __shfl_xor_sync(0xffffffffu, rs0, 2);
        rs1 += __shfl_xor_sync(0xffffffffu, rs1, 1);
        rs1 += __shfl_xor_sync(0xffffffffu, rs1, 2);

        lrow0 = lrow0 * alpha0 + rs0;  mrow0 = mnew0;
        lrow1 = lrow1 * alpha1 + rs1;  mrow1 = mnew1;
#pragma unroll
        for (int nf = 0; nf < 8; nf++) {
            o[nf][0] *= alpha0; o[nf][1] *= alpha0;
            o[nf][2] *= alpha1; o[nf][3] *= alpha1;
        }
        __syncwarp();   // P writes visible to warp before ldmatrix

        // ---- O += P V : m16 x n64 (full hs), contract warp's 32 keys ----
#pragma unroll
        for (int kf = 0; kf < 4; kf++) {
            int kb = kf * 8;
            uint32_t a0, a1, a2, a3;
            uint32_t aaddr = pbase + ((m0 + arow) * PS_P + n0 + kb + acol) * 4;
            LDSM_X4(a0, a1, a2, a3, aaddr);
#pragma unroll
            for (int nfp = 0; nfp < 4; nfp++) {
                uint32_t b0, b1, b2, b3;
                uint32_t vaddr = vtst +
                    ((nfp * 16 + brow) * VT_P + n0 + kb + bcol) * 4;
                LDSM_X4(b0, b1, b2, b3, vaddr);
                mma_tf32(o[nfp * 2],     a0, a1, a2, a3, b0, b1);
                mma_tf32(o[nfp * 2 + 1], a0, a1, a2, a3, b2, b3);
            }
        }
    }

    // ---- merge key-halves: wn=1 publishes (o, m, l); wn=0 combines ----
    float* Pf = reinterpret_cast<float*>(hsm + OFF_P);
    BARH(barid);
    if (wn == 1) {
#pragma unroll
        for (int nf = 0; nf < 8; nf++) {
            int c0 = nf * 8 + 2 * t4;
            Pf[(m0 + g) * PS_P + c0]         = o[nf][0];
            Pf[(m0 + g) * PS_P + c0 + 1]     = o[nf][1];
            Pf[(m0 + g + 8) * PS_P + c0]     = o[nf][2];
            Pf[(m0 + g + 8) * PS_P + c0 + 1] = o[nf][3];
        }
        if (t4 == 0) {
            Pf[(m0 + g) * PS_P + 64] = mrow0;
            Pf[(m0 + g) * PS_P + 65] = lrow0;
            Pf[(m0 + g + 8) * PS_P + 64] = mrow1;
            Pf[(m0 + g + 8) * PS_P + 65] = lrow1;
        }
    }
    BARH(barid);
    if (wn == 0) {
        float m1_0 = Pf[(m0 + g) * PS_P + 64];
        float l1_0 = Pf[(m0 + g) * PS_P + 65];
        float m1_1 = Pf[(m0 + g + 8) * PS_P + 64];
        float l1_1 = Pf[(m0 + g + 8) * PS_P + 65];

        float M0 = fmaxf(mrow0, m1_0);
        float w00 = __expf(mrow0 - M0), w10 = __expf(m1_0 - M0);
        float inv0 = 1.f / (lrow0 * w00 + l1_0 * w10);
        float s00 = w00 * inv0, s10 = w10 * inv0;

        float M1 = fmaxf(mrow1, m1_1);
        float w01 = __expf(mrow1 - M1), w11 = __expf(m1_1 - M1);
        float inv1 = 1.f / (lrow1 * w01 + l1_1 * w11);
        float s01 = w01 * inv1, s11 = w11 * inv1;

        const int row = q0 + m0 + g;
#pragma unroll
        for (int nf = 0; nf < 8; nf++) {
            int c0 = nf * 8 + 2 * t4;
            float u0 = o[nf][0] * s00 + Pf[(m0 + g) * PS_P + c0]     * s10;
            float u1 = o[nf][1] * s00 + Pf[(m0 + g) * PS_P + c0 + 1] * s10;
            float u2 = o[nf][2] * s01 + Pf[(m0 + g + 8) * PS_P + c0]     * s11;
            float u3 = o[nf][3] * s01 + Pf[(m0 + g + 8) * PS_P + c0 + 1] * s11;
            *reinterpret_cast<float2*>(&out[((size_t)b * TT + row) * HS + c0]) =
                make_float2(u0, u1);
            *reinterpret_cast<float2*>(&out[((size_t)b * TT + row + 8) * HS + c0]) =
                make_float2(u2, u3);
        }
    }
}

// ---------------------------------------------------------------------------
extern "C" void kernel_launch(void* const* d_in, const int* in_sizes, int n_in,
                              void* d_out, int out_size) {
    const float* x  = (const float*)d_in[0];
    const float* Wq = (const float*)d_in[1];
    const float* bq = (const float*)d_in[2];
    const float* Wk = (const float*)d_in[3];
    const float* bk = (const float*)d_in[4];
    const float* Wv = (const float*)d_in[5];
    const float* bv = (const float*)d_in[6];
    float* out = (float*)d_out;

    cudaFuncSetAttribute(flash_attn, cudaFuncAttributeMaxDynamicSharedMemorySize,
                         SMEM_BYTES);

    qkv_proj<<<(BB * TT) / 64, 256>>>(x, Wq, bq, Wk, bk, Wv, bv);
    flash_attn<<<dim3(16, BB), 512, SMEM_BYTES>>>(out);
}